// round 16
// baseline (speedup 1.0000x reference)
#include <cuda_runtime.h>
#include <cuda_bf16.h>
#include <math.h>
#include <stdint.h>

// ---------------------------------------------------------------------------
// GCN: 3x GCNConv(+lrelu) -> reshape(40/graph) -> 3x Linear -> sigmoid
// GEMMs: mma.sync m16n8k16 bf16x3 emulation, ldmatrix fragments, cp.async,
// 3-stage smem ring with XOR swizzle, one barrier per k-chunk.
// Aggregation: dst-CSR gather with norm folding. Deterministic split-K (z=8).
// CSR build: single-pass decoupled-lookback scan; convW fused with fill_csr.
// ---------------------------------------------------------------------------

#define TILE_M 128
#define TILE_N 128
#define KC 32
#define SROW 64
#define ARR_BYTES (128 * SROW)
#define SOFF_AH 0
#define SOFF_AL (1 * ARR_BYTES)
#define SOFF_WH (2 * ARR_BYTES)
#define SOFF_WL (3 * ARR_BYTES)
#define STAGE_STRIDE (4 * ARR_BYTES)
#define SMB (3 * STAGE_STRIDE)        // 98304

#define NMAX 200000
#define EMAX 1000000

__device__ __align__(256) float g_bufA[(size_t)NMAX * 128];
__device__ __align__(256) float g_bufC[(size_t)NMAX * 32];
__device__ __align__(256) float g_dis[NMAX];
__device__ __align__(256) __nv_bfloat16 g_whi[2760000];
__device__ __align__(256) __nv_bfloat16 g_wlo[2760000];
__device__ __align__(256) __nv_bfloat16 g_hiA[(size_t)NMAX * 256];
__device__ __align__(256) __nv_bfloat16 g_loA[(size_t)NMAX * 256];
__device__ __align__(256) __nv_bfloat16 g_hiB[(size_t)NMAX * 128];
__device__ __align__(256) __nv_bfloat16 g_loB[(size_t)NMAX * 128];
__device__ __align__(256) int g_ptr[NMAX + 1];
__device__ __align__(256) int g_cursor[NMAX];
__device__ __align__(256) int g_csr[EMAX];
__device__ __align__(256) int g_status[256];

__device__ __forceinline__ float lrelu_f(float v) { return v > 0.f ? v : 0.1f * v; }

__device__ __forceinline__ uint32_t smem_u32(const void* p) {
    uint32_t a;
    asm("{ .reg .u64 t; cvta.to.shared.u64 t, %1; cvt.u32.u64 %0, t; }" : "=r"(a) : "l"(p));
    return a;
}
__device__ __forceinline__ void mma16816(float* c, const uint32_t* a, const uint32_t* b) {
    asm volatile(
        "mma.sync.aligned.m16n8k16.row.col.f32.bf16.bf16.f32 "
        "{%0,%1,%2,%3}, {%4,%5,%6,%7}, {%8,%9}, {%0,%1,%2,%3};"
        : "+f"(c[0]), "+f"(c[1]), "+f"(c[2]), "+f"(c[3])
        : "r"(a[0]), "r"(a[1]), "r"(a[2]), "r"(a[3]), "r"(b[0]), "r"(b[1]));
}
#define LDMX4(r, addr) \
    asm volatile("ldmatrix.sync.aligned.m8n8.x4.shared.b16 {%0,%1,%2,%3}, [%4];" \
        : "=r"((r)[0]), "=r"((r)[1]), "=r"((r)[2]), "=r"((r)[3]) : "r"(addr))
__device__ __forceinline__ void cp16(uint32_t dst, const void* src, int srcsize) {
    asm volatile("cp.async.cg.shared.global [%0], [%1], 16, %2;"
                 :: "r"(dst), "l"(src), "r"(srcsize) : "memory");
}
#define CP_COMMIT() asm volatile("cp.async.commit_group;" ::: "memory")
#define CP_WAIT0()  asm volatile("cp.async.wait_group 0;" ::: "memory")
#define CP_WAIT1()  asm volatile("cp.async.wait_group 1;" ::: "memory")

__device__ __forceinline__ void split2(float c0, float c1, uint32_t& hp, uint32_t& lp) {
    __nv_bfloat16 h0 = __float2bfloat16_rn(c0), h1 = __float2bfloat16_rn(c1);
    __nv_bfloat16 l0 = __float2bfloat16_rn(c0 - __bfloat162float(h0));
    __nv_bfloat16 l1 = __float2bfloat16_rn(c1 - __bfloat162float(h1));
    hp = (uint32_t)__bfloat16_as_ushort(h0) | ((uint32_t)__bfloat16_as_ushort(h1) << 16);
    lp = (uint32_t)__bfloat16_as_ushort(l0) | ((uint32_t)__bfloat16_as_ushort(l1) << 16);
}

// --------------------------- CSR build kernels ------------------------------
__global__ void k_zero(int* cursor, int* status, int n) {
    int i = blockIdx.x * blockDim.x + threadIdx.x;
    if (i < n) cursor[i] = 0;
    if (i < 256) status[i] = 0;
}
__global__ void k_hist(int* cnt, const int* __restrict__ dst, int E) {
    int e = blockIdx.x * blockDim.x + threadIdx.x;
    if (e < E) atomicAdd(&cnt[dst[e]], 1);
}
// Single-pass exclusive scan (decoupled lookback). cnt -> ptr (+copy cursor),
// also dis[i] = rsqrt(cnt[i]+1). status[] must be zeroed. Flags: bit31=prefix,
// bit30=aggregate; low 30 bits = value. All blocks co-resident (nb<=296).
__global__ void k_scan_lookback(int* __restrict__ cnt, int* __restrict__ ptr,
                                int* __restrict__ cursor, float* __restrict__ dis,
                                volatile int* status, int n)
{
    __shared__ int sm[1024];
    __shared__ int shExcl;
    int i = blockIdx.x * 1024 + threadIdx.x;
    int v = (i < n) ? cnt[i] : 0;
    if (i < n) dis[i] = rsqrtf((float)v + 1.0f);
    sm[threadIdx.x] = v;
    __syncthreads();
    for (int off = 1; off < 1024; off <<= 1) {
        int t = (threadIdx.x >= off) ? sm[threadIdx.x - off] : 0;
        __syncthreads();
        sm[threadIdx.x] += t;
        __syncthreads();
    }
    if (threadIdx.x == 1023) {
        int total = sm[1023];
        int excl = 0;
        if (blockIdx.x == 0) {
            ((volatile int*)status)[0] = 0x80000000 | total;
        } else {
            ((volatile int*)status)[blockIdx.x] = 0x40000000 | total;
            int j = (int)blockIdx.x - 1;
            while (j >= 0) {
                int s = ((volatile int*)status)[j];
                if (s & 0x80000000) { excl += s & 0x3fffffff; break; }
                if (s & 0x40000000) { excl += s & 0x3fffffff; j--; }
            }
            ((volatile int*)status)[blockIdx.x] = 0x80000000 | (excl + total);
        }
        shExcl = excl;
        if (blockIdx.x == gridDim.x - 1) ptr[n] = excl + total;
    }
    __syncthreads();
    if (i < n) {
        int p = sm[threadIdx.x] - v + shExcl;
        ptr[i] = p;
        cursor[i] = p;
    }
}
// Fused: CSR fill (first eBlocks) + weight fp32->bf16 hi/lo split (rest).
__global__ void k_fill_convW(const int* __restrict__ src, const int* __restrict__ dst,
                             int* cursor, int* __restrict__ csr, int E, int eBlocks,
                             const float* __restrict__ W1, const float* __restrict__ W2,
                             const float* __restrict__ W3, const float* __restrict__ L1w,
                             const float* __restrict__ L2w,
                             __nv_bfloat16* __restrict__ hi, __nv_bfloat16* __restrict__ lo)
{
    if ((int)blockIdx.x < eBlocks) {
        int e = blockIdx.x * 256 + threadIdx.x;
        if (e < E) {
            int pos = atomicAdd(&cursor[dst[e]], 1);
            csr[pos] = src[e];
        }
        return;
    }
    const int n1 = 5120, n2 = n1 + 32768, n3 = n2 + 32768,
              n4 = n3 + 2621440, n5 = n4 + 65536;
    int i = ((int)blockIdx.x - eBlocks) * 256 + threadIdx.x;
    if (i >= n5) return;
    float v;
    if      (i < n1) v = W1[i];
    else if (i < n2) v = W2[i - n1];
    else if (i < n3) v = W3[i - n2];
    else if (i < n4) v = L1w[i - n3];
    else             v = L2w[i - n4];
    __nv_bfloat16 h = __float2bfloat16_rn(v);
    hi[i] = h;
    lo[i] = __float2bfloat16_rn(v - __bfloat162float(h));
}

// ---------------------------- split-K reduce --------------------------------
__global__ void k_reduce_split(const float* __restrict__ P, const float* __restrict__ bias,
                               __nv_bfloat16* __restrict__ Ohi, __nv_bfloat16* __restrict__ Olo,
                               int total, int ncols, int nsplit)
{
    int i = blockIdx.x * blockDim.x + threadIdx.x;
    if (i >= total) return;
    float s = bias[i % ncols];
    for (int z = 0; z < nsplit; z++) s += P[(long long)z * total + i];
    float v = lrelu_f(s);
    __nv_bfloat16 h = __float2bfloat16_rn(v);
    Ohi[i] = h;
    Olo[i] = __float2bfloat16_rn(v - __bfloat162float(h));
}

// ------------------------------ CSR gathers ---------------------------------
__global__ void __launch_bounds__(256)
k_gather128(const float* __restrict__ H, const float* __restrict__ aggb,
            __nv_bfloat16* __restrict__ Ohi, __nv_bfloat16* __restrict__ Olo,
            const int* __restrict__ ptr, const int* __restrict__ csr,
            const float* __restrict__ dis, int Nn, int doLrelu)
{
    int node = (int)(((long long)blockIdx.x * blockDim.x + threadIdx.x) >> 5);
    int lane = threadIdx.x & 31;
    if (node >= Nn) return;

    int p0 = ptr[node];
    int p1 = ptr[node + 1];
    float dn = dis[node];

    float4 acc = *(const float4*)(H + (long long)node * 128 + lane * 4);
    int p = p0;
    for (; p + 3 < p1; p += 4) {
        int s0 = csr[p], s1 = csr[p + 1], s2 = csr[p + 2], s3 = csr[p + 3];
        float4 v0 = *(const float4*)(H + (long long)s0 * 128 + lane * 4);
        float4 v1 = *(const float4*)(H + (long long)s1 * 128 + lane * 4);
        float4 v2 = *(const float4*)(H + (long long)s2 * 128 + lane * 4);
        float4 v3 = *(const float4*)(H + (long long)s3 * 128 + lane * 4);
        acc.x += (v0.x + v1.x) + (v2.x + v3.x);
        acc.y += (v0.y + v1.y) + (v2.y + v3.y);
        acc.z += (v0.z + v1.z) + (v2.z + v3.z);
        acc.w += (v0.w + v1.w) + (v2.w + v3.w);
    }
    for (; p < p1; p++) {
        int s0 = csr[p];
        float4 v0 = *(const float4*)(H + (long long)s0 * 128 + lane * 4);
        acc.x += v0.x; acc.y += v0.y; acc.z += v0.z; acc.w += v0.w;
    }
    acc.x *= dn; acc.y *= dn; acc.z *= dn; acc.w *= dn;
    if (aggb) {
        float4 bv = *(const float4*)(aggb + lane * 4);
        acc.x += bv.x; acc.y += bv.y; acc.z += bv.z; acc.w += bv.w;
    }
    if (doLrelu) {
        acc.x = lrelu_f(acc.x); acc.y = lrelu_f(acc.y);
        acc.z = lrelu_f(acc.z); acc.w = lrelu_f(acc.w);
    }
    uint32_t h0, l0, h1, l1;
    split2(acc.x, acc.y, h0, l0);
    split2(acc.z, acc.w, h1, l1);
    long long o = (long long)node * 128 + lane * 4;
    *(uint2*)(Ohi + o) = make_uint2(h0, h1);
    *(uint2*)(Olo + o) = make_uint2(l0, l1);
}

__global__ void __launch_bounds__(256)
k_gather40(const float* __restrict__ X,
           __nv_bfloat16* __restrict__ Ohi, __nv_bfloat16* __restrict__ Olo,
           const int* __restrict__ ptr, const int* __restrict__ csr,
           const float* __restrict__ dis, int Nn)
{
    int node = (int)(((long long)blockIdx.x * blockDim.x + threadIdx.x) >> 5);
    int lane = threadIdx.x & 31;
    if (node >= Nn) return;

    int p0 = ptr[node];
    int p1 = ptr[node + 1];
    float dn = dis[node];
    float d2 = dn * dn;

    long long base = (long long)node * 40;
    float a0 = X[base + lane] * d2;
    float a1 = (lane < 8) ? X[base + 32 + lane] * d2 : 0.f;
    int p = p0;
    for (; p + 1 < p1; p += 2) {
        int s0 = csr[p], s1 = csr[p + 1];
        float n0 = dn * dis[s0], n1 = dn * dis[s1];
        long long hb0 = (long long)s0 * 40, hb1 = (long long)s1 * 40;
        a0 += X[hb0 + lane] * n0 + X[hb1 + lane] * n1;
        if (lane < 8) a1 += X[hb0 + 32 + lane] * n0 + X[hb1 + 32 + lane] * n1;
    }
    if (p < p1) {
        int s = csr[p];
        float nm = dn * dis[s];
        long long hb = (long long)s * 40;
        a0 += X[hb + lane] * nm;
        if (lane < 8) a1 += X[hb + 32 + lane] * nm;
    }
    __nv_bfloat16 h = __float2bfloat16_rn(a0);
    Ohi[base + lane] = h;
    Olo[base + lane] = __float2bfloat16_rn(a0 - __bfloat162float(h));
    if (lane < 8) {
        __nv_bfloat16 h1 = __float2bfloat16_rn(a1);
        Ohi[base + 32 + lane] = h1;
        Olo[base + 32 + lane] = __float2bfloat16_rn(a1 - __bfloat162float(h1));
    }
}

// ------------------------ tensor-core bf16x3 GEMM ---------------------------
__global__ void __launch_bounds__(256, 2)
k_mma_gemm(const __nv_bfloat16* __restrict__ Ahi, const __nv_bfloat16* __restrict__ Alo,
           const __nv_bfloat16* __restrict__ Whi, const __nv_bfloat16* __restrict__ Wlo,
           float* __restrict__ H,
           __nv_bfloat16* __restrict__ Ohi, __nv_bfloat16* __restrict__ Olo,
           const float* __restrict__ bias, const float* __restrict__ rowScale,
           int M, int Nout, int K, int kLen, int lreluOut, int kSplit)
{
    extern __shared__ __align__(128) char smem[];
    const uint32_t sb = smem_u32(smem);
    const int tid  = threadIdx.x;
    const int wid  = tid >> 5;
    const int lane = tid & 31;
    const int g    = lane >> 2;
    const int tig  = lane & 3;
    const int warpM = wid >> 1;
    const int warpN = wid & 1;
    const int mBase = blockIdx.y * TILE_M;
    const int nBase = blockIdx.x * TILE_N;
    const long long zOff = (long long)blockIdx.z * kLen;

    float acc[2][8][4];
#pragma unroll
    for (int i = 0; i < 2; i++)
#pragma unroll
        for (int j = 0; j < 8; j++)
#pragma unroll
            for (int q = 0; q < 4; q++) acc[i][j][q] = 0.f;

    uint32_t aAddrH[2], aAddrL[2], bAddrH[2][2], bAddrL[2][2];
    {
#pragma unroll
        for (int ms = 0; ms < 2; ms++) {
            uint32_t row = (uint32_t)(warpM * 32 + ms * 16 + (lane & 15));
            uint32_t sw  = (row >> 1) & 3;
            uint32_t off = row * SROW + (((lane >> 4) ^ sw) << 4);
            aAddrH[ms] = sb + SOFF_AH + off;
            aAddrL[ms] = sb + SOFF_AL + off;
        }
        uint32_t bR0 = (uint32_t)(warpN * 64 + ((lane >> 4) & 1) * 8 + (lane & 7));
        uint32_t g0  = (lane >> 3) & 1;
#pragma unroll
        for (int nh = 0; nh < 2; nh++)
#pragma unroll
            for (int p = 0; p < 2; p++) {
                uint32_t row = bR0 + (uint32_t)(nh * 32 + p * 16);
                uint32_t sw  = (row >> 1) & 3;
                uint32_t off = row * SROW + ((g0 ^ sw) << 4);
                bAddrH[nh][p] = sb + SOFF_WH + off;
                bAddrL[nh][p] = sb + SOFF_WL + off;
            }
    }

    auto issueStage = [&](int stg, int kb) {
        const uint32_t so = sb + (uint32_t)(stg * STAGE_STRIDE);
#pragma unroll
        for (int q = tid; q < 512; q += 256) {
            int row = q >> 2, kg = q & 3;
            long long gk = zOff + kb + kg * 8;
            uint32_t sw   = ((uint32_t)row >> 1) & 3;
            uint32_t doff = (uint32_t)(row * SROW) + (((uint32_t)kg ^ sw) << 4);
            {
                int gm = mBase + row;
                bool ok = (gm < M) && (gk + 8 <= (long long)K);
                long long aoff = ok ? ((long long)gm * K + gk) : 0;
                int ss = ok ? 16 : 0;
                cp16(so + SOFF_AH + doff, Ahi + aoff, ss);
                cp16(so + SOFF_AL + doff, Alo + aoff, ss);
            }
            {
                bool ok = (gk + 8 <= (long long)K);
                long long woff = ok ? ((long long)(nBase + row) * K + gk) : 0;
                int ss = ok ? 16 : 0;
                cp16(so + SOFF_WH + doff, Whi + woff, ss);
                cp16(so + SOFF_WL + doff, Wlo + woff, ss);
            }
        }
    };

    issueStage(0, 0);
    CP_COMMIT();
    if (KC < kLen) { issueStage(1, KC); CP_COMMIT(); }

    int s = 0;
    for (int kb = 0; kb < kLen; kb += KC) {
        if (kb + KC >= kLen) CP_WAIT0(); else CP_WAIT1();
        __syncthreads();

        const int kn = kb + 2 * KC;
        if (kn < kLen) {
            int s2 = s + 2; if (s2 >= 3) s2 -= 3;
            issueStage(s2, kn);
            CP_COMMIT();
        }

        const uint32_t so = (uint32_t)(s * STAGE_STRIDE);
#pragma unroll
        for (int kk = 0; kk < 2; kk++) {
            const uint32_t kx = (uint32_t)(kk << 5);
            uint32_t AH[2][4], AL[2][4];
#pragma unroll
            for (int ms = 0; ms < 2; ms++) {
                LDMX4(AH[ms], (aAddrH[ms] + so) ^ kx);
                LDMX4(AL[ms], (aAddrL[ms] + so) ^ kx);
            }
#pragma unroll
            for (int nh = 0; nh < 2; nh++) {
#pragma unroll
                for (int p = 0; p < 2; p++) {
                    uint32_t BH[4], BL[4];
                    LDMX4(BH, (bAddrH[nh][p] + so) ^ kx);
                    LDMX4(BL, (bAddrL[nh][p] + so) ^ kx);
                    const int j0 = nh * 4 + p * 2;
#pragma unroll
                    for (int ms = 0; ms < 2; ms++) {
                        mma16816(acc[ms][j0],     AH[ms], BH);
                        mma16816(acc[ms][j0],     AH[ms], BL);
                        mma16816(acc[ms][j0],     AL[ms], BH);
                        mma16816(acc[ms][j0 + 1], AH[ms], BH + 2);
                        mma16816(acc[ms][j0 + 1], AH[ms], BL + 2);
                        mma16816(acc[ms][j0 + 1], AL[ms], BH + 2);
                    }
                }
            }
        }
        s = (s == 2) ? 0 : s + 1;
    }

    const int mW = mBase + warpM * 32;
    const long long zPart = (long long)blockIdx.z * M * Nout;
#pragma unroll
    for (int ms = 0; ms < 2; ms++) {
#pragma unroll
        for (int half = 0; half < 2; half++) {
            int row = mW + ms * 16 + g + half * 8;
            if (row >= M) continue;
            long long ro = (long long)row * Nout;
            float rs = 1.f;
            if (rowScale) rs = rowScale[row];
#pragma unroll
            for (int ns = 0; ns < 8; ns++) {
                int col = nBase + warpN * 64 + ns * 8 + 2 * tig;
                float c0 = acc[ms][ns][half * 2 + 0];
                float c1 = acc[ms][ns][half * 2 + 1];
                if (kSplit > 1) {
                    *(float2*)(H + zPart + ro + col) = make_float2(c0, c1);
                } else {
                    if (bias) { c0 += __ldg(&bias[col]); c1 += __ldg(&bias[col + 1]); }
                    if (lreluOut) { c0 = lrelu_f(c0); c1 = lrelu_f(c1); }
                    if (Ohi) {
                        uint32_t hp, lp;
                        split2(c0, c1, hp, lp);
                        *(uint32_t*)(Ohi + ro + col) = hp;
                        *(uint32_t*)(Olo + ro + col) = lp;
                    } else {
                        *(float2*)(H + ro + col) = make_float2(c0 * rs, c1 * rs);
                    }
                }
            }
        }
    }
}

// ---------------- final linear + sigmoid (fused L2 split-K reduce) -----------
__global__ void k_mlp_out(const float* __restrict__ P, const float* __restrict__ L2b,
                          const float* __restrict__ L3w, const float* __restrict__ L3b,
                          float* __restrict__ out, int G, int nsplit)
{
    int w    = (blockIdx.x * blockDim.x + threadIdx.x) >> 5;
    int lane = threadIdx.x & 31;
    if (w >= G) return;
    const int total = G * 128;
    float s = 0.f;
#pragma unroll
    for (int c = lane; c < 128; c += 32) {
        float v = __ldg(&L2b[c]);
        long long idx = (long long)w * 128 + c;
        for (int z = 0; z < nsplit; z++) v += P[(long long)z * total + idx];
        s += lrelu_f(v) * __ldg(&L3w[c]);
    }
#pragma unroll
    for (int off = 16; off; off >>= 1) s += __shfl_xor_sync(0xffffffffu, s, off);
    if (lane == 0) out[w] = 1.f / (1.f + expf(-(s + L3b[0])));
}

// ------------------------------- launch ------------------------------------
extern "C" void kernel_launch(void* const* d_in, const int* in_sizes, int n_in,
                              void* d_out, int out_size)
{
    const float* x   = (const float*)d_in[0];
    const int*   ei  = (const int*)d_in[1];
    const float* b1 = (const float*)d_in[3];
    const float* b2 = (const float*)d_in[5];
    const float* b3 = (const float*)d_in[7];
    const float* L1b = (const float*)d_in[9];
    const float* L2b = (const float*)d_in[11];
    const float* L3w = (const float*)d_in[12]; const float* L3b = (const float*)d_in[13];
    float* out = (float*)d_out;

    const int C = 40;
    const int N = in_sizes[0] / C;     // 200000
    const int E = in_sizes[1] / 2;     // 1000000
    const int G = N / 40;              // 5000

    const int* srcIdx = ei;
    const int* dstIdx = ei + E;

    float *bufA, *bufC, *dis;
    __nv_bfloat16 *whi, *wlo, *hiA, *loA, *hiB, *loB;
    int *ptr, *cursor, *csr, *status;
    cudaGetSymbolAddress((void**)&bufA, g_bufA);
    cudaGetSymbolAddress((void**)&bufC, g_bufC);
    cudaGetSymbolAddress((void**)&dis,  g_dis);
    cudaGetSymbolAddress((void**)&whi,  g_whi);
    cudaGetSymbolAddress((void**)&wlo,  g_wlo);
    cudaGetSymbolAddress((void**)&hiA,  g_hiA);
    cudaGetSymbolAddress((void**)&loA,  g_loA);
    cudaGetSymbolAddress((void**)&hiB,  g_hiB);
    cudaGetSymbolAddress((void**)&loB,  g_loB);
    cudaGetSymbolAddress((void**)&ptr,    g_ptr);
    cudaGetSymbolAddress((void**)&cursor, g_cursor);
    cudaGetSymbolAddress((void**)&csr,    g_csr);
    cudaGetSymbolAddress((void**)&status, g_status);

    cudaFuncSetAttribute(k_mma_gemm, cudaFuncAttributeMaxDynamicSharedMemorySize, SMB);

    const int O1 = 0;
    const int O2 = O1 + 128 * 40;
    const int O3 = O2 + 256 * 128;
    const int O4 = O3 + 128 * 256;
    const int O5 = O4 + 512 * 5120;
    const int WTOT = O5 + 128 * 512;   // 2757632

    // ---- CSR build + degree normalization + weight conversion ----
    const int nb = (N + 1023) / 1024;            // 196 (<=296: lookback-safe)
    k_zero<<<(N + 255) / 256, 256>>>(cursor, status, N);
    k_hist<<<(E + 255) / 256, 256>>>(cursor, dstIdx, E);
    k_scan_lookback<<<nb, 1024>>>(cursor, ptr, cursor, dis, status, N);
    const int eBlocks = (E + 255) / 256;
    const int wBlocks = (WTOT + 255) / 256;
    k_fill_convW<<<eBlocks + wBlocks, 256>>>(
        srcIdx, dstIdx, cursor, csr, E, eBlocks,
        (const float*)d_in[2], (const float*)d_in[4], (const float*)d_in[6],
        (const float*)d_in[8], (const float*)d_in[10], whi, wlo);

    const int mTilesN = (N + 127) / 128;   // 1563
    const int mTilesG = (G + 127) / 128;   // 40
    const int gatherBlocks = (int)(((long long)N * 32 + 255) / 256);

    // ---- conv1 (aggregate-first): A1 = Âx -> presplit hiA/loA [N,40] ----
    k_gather40<<<gatherBlocks, 256>>>(x, hiA, loA, ptr, csr, dis, N);
    // GEMM1: P1' = lrelu(A1@W1^T + b1) * dis -> bufA fp32 [N,128]
    k_mma_gemm<<<dim3(1, mTilesN, 1), 256, SMB>>>(
        hiA, loA, whi + O1, wlo + O1, bufA, nullptr, nullptr,
        b1, dis, N, 128, 40, 64, 1, 1);

    // ---- conv2: A2 = dis*(P1'[d] + sum P1'[s]) -> hiB/loB ----
    k_gather128<<<gatherBlocks, 256>>>(bufA, nullptr, hiB, loB, ptr, csr, dis, N, 0);
    // GEMM2: lrelu(A2@W2^T + b2) -> presplit hiA/loA [N,256]
    k_mma_gemm<<<dim3(2, mTilesN, 1), 256, SMB>>>(
        hiB, loB, whi + O2, wlo + O2, nullptr, hiA, loA,
        b2, nullptr, N, 256, 128, 128, 1, 1);

    // ---- conv3 (transform-first): H3' = (in@W3^T)*dis -> bufA fp32 [N,128] ----
    k_mma_gemm<<<dim3(1, mTilesN, 1), 256, SMB>>>(
        hiA, loA, whi + O3, wlo + O3, bufA, nullptr, nullptr,
        nullptr, dis, N, 128, 256, 256, 0, 1);
    // gather: AGG3 = dis*(H3'[d] + sum H3'[s]) + b3, lrelu, presplit
    k_gather128<<<gatherBlocks, 256>>>(bufA, b3, hiB, loB, ptr, csr, dis, N, 1);

    // ---- MLP ----
    // L1 split-K x8 -> partials in bufA [8][G,512]; reduce -> presplit hiA/loA
    k_mma_gemm<<<dim3(4, mTilesG, 8), 256, SMB>>>(
        hiB, loB, whi + O4, wlo + O4, bufA, nullptr, nullptr,
        nullptr, nullptr, G, 512, 5120, 640, 0, 8);
    k_reduce_split<<<(G * 512 + 255) / 256, 256>>>(
        bufA, L1b, hiA, loA, G * 512, 512, 8);
    // L2 split-K x8 -> partials in bufC [8][G,128]; reduce fused into mlp_out
    k_mma_gemm<<<dim3(1, mTilesG, 8), 256, SMB>>>(
        hiA, loA, whi + O5, wlo + O5, bufC, nullptr, nullptr,
        nullptr, nullptr, G, 128, 512, 64, 0, 8);
    k_mlp_out<<<(G * 32 + 255) / 256, 256>>>(bufC, L2b, L3w, L3b, out, G, 8);
}